// round 8
// baseline (speedup 1.0000x reference)
#include <cuda_runtime.h>
#include <cuda_bf16.h>
#include <cuda_fp16.h>
#include <cstdint>

#define BB 8
#define KN 512
#define QN 128
#define DD 256
#define NEGC (-1000000.0f)

// scratch
__device__ __half g_qproj[BB * QN * DD];                 // [b*128+q][h]     512KB
__device__ __half g_kprojT[BB * (DD / 8) * KN * 8];      // [b][h/8][k][h%8]   2MB
__device__ float  g_atten[BB * QN * KN];                 // [b][q][k]          2MB

__device__ __forceinline__ unsigned int htanh2(unsigned int x) {
    unsigned int y;
    asm("tanh.approx.f16x2 %0, %1;" : "=r"(y) : "r"(x));
    return y;
}
__device__ __forceinline__ unsigned int hadd2u(unsigned int a, unsigned int b) {
    unsigned int r;
    asm("add.f16x2 %0, %1, %2;" : "=r"(r) : "r"(a), "r"(b));
    return r;
}
__device__ __forceinline__ unsigned int packf2(float2 v) {
    __half2 h = __floats2half2_rn(v.x, v.y);
    return *(unsigned int*)&h;
}
__device__ __forceinline__ void mma16816(float c[4],
    unsigned int a0, unsigned int a1, unsigned int a2, unsigned int a3,
    unsigned int b0, unsigned int b1)
{
    asm("mma.sync.aligned.m16n8k16.row.col.f32.f16.f16.f32 "
        "{%0,%1,%2,%3}, {%4,%5,%6,%7}, {%8,%9}, {%0,%1,%2,%3};"
        : "+f"(c[0]), "+f"(c[1]), "+f"(c[2]), "+f"(c[3])
        : "r"(a0), "r"(a1), "r"(a2), "r"(a3), "r"(b0), "r"(b1));
}

// ---------------------------------------------------------------------------
// Kernel 1: projection GEMM on tensor cores (fp16 in, fp32 accum).
// C[m][h] = sum_d A[m][d] * W_hidden[h][off + d]
// Block tile 64m x 64n, 8 warps (warp tile 16m x 32n), grid 320 -> 2-3 blk/SM.
// ---------------------------------------------------------------------------
__global__ __launch_bounds__(256) void proj_kernel(
    const float* __restrict__ queries,
    const float* __restrict__ keys,
    const float* __restrict__ W_hidden)
{
    __shared__ __half cs[64][72];        // 144B pitch (16B-aligned rows)

    const int tid  = threadIdx.x;
    const int wid  = tid >> 5;
    const int lane = tid & 31;
    const int m0 = blockIdx.x * 64;      // 80 m-blocks (16 Q, 64 K)
    const int n0 = blockIdx.y * 64;      // 4 n-blocks
    const bool isQ = (m0 < BB * QN);
    const float* A = isQ ? (queries + (size_t)m0 * DD)
                         : (keys + (size_t)(m0 - BB * QN) * DD);
    const int off = isQ ? 0 : DD;

    const int wm = (wid & 3) * 16;       // 0..48
    const int wn = (wid >> 2) * 32;      // 0 / 32
    const int g  = lane >> 2;            // 0..7
    const int kq = (lane & 3) * 2;       // 0,2,4,6

    float c[4][4] = {};

    #pragma unroll 4
    for (int k16 = 0; k16 < DD; k16 += 16) {
        unsigned int a[4];
        {
            const float* ap = A + (size_t)(wm + g) * DD + k16 + kq;
            a[0] = packf2(*(const float2*)(ap));
            a[1] = packf2(*(const float2*)(ap + 8 * DD));
            a[2] = packf2(*(const float2*)(ap + 8));
            a[3] = packf2(*(const float2*)(ap + 8 * DD + 8));
        }
        unsigned int b[4][2];
        #pragma unroll
        for (int nf = 0; nf < 4; nf++) {
            const float* bp = W_hidden + (size_t)(n0 + wn + nf * 8 + g) * (2 * DD) + off + k16 + kq;
            b[nf][0] = packf2(*(const float2*)(bp));
            b[nf][1] = packf2(*(const float2*)(bp + 8));
        }
        #pragma unroll
        for (int nf = 0; nf < 4; nf++)
            mma16816(c[nf], a[0], a[1], a[2], a[3], b[nf][0], b[nf][1]);
    }

    // stage to smem as half
    {
        int r0 = wm + g;
        #pragma unroll
        for (int nf = 0; nf < 4; nf++) {
            int col = wn + nf * 8 + (lane & 3) * 2;
            *(__half2*)&cs[r0][col]     = __floats2half2_rn(c[nf][0], c[nf][1]);
            *(__half2*)&cs[r0 + 8][col] = __floats2half2_rn(c[nf][2], c[nf][3]);
        }
    }
    __syncthreads();

    if (isQ) {
        // 64 rows x 64 halves = 512 x 16B chunks, 2 per thread
        #pragma unroll
        for (int i = 0; i < 2; i++) {
            int id = tid + i * 256;
            int row = id >> 3, seg = id & 7;
            *(uint4*)&g_qproj[(size_t)(m0 + row) * DD + n0 + seg * 8] =
                *(const uint4*)&cs[row][seg * 8];
        }
    } else {
        // 64 k-rows x 8 h-chunks = 512 x 16B chunks, 2 per thread
        #pragma unroll
        for (int i = 0; i < 2; i++) {
            int id = tid + i * 256;
            int cc = id >> 6, krow = id & 63;
            int krg = m0 - BB * QN + krow;
            int b = krg >> 9, k = krg & (KN - 1);
            *(uint4*)&g_kprojT[(size_t)(((b * 32 + (n0 >> 3) + cc) * KN) + k) * 8] =
                *(const uint4*)&cs[krow][cc * 8];
        }
    }
}

// ---------------------------------------------------------------------------
// Kernel 2: logits (f16x2 tanh) + masked softmax -> g_atten.
// Block = (b, 4 queries). 256 threads, each owns k=tid and k=tid+256.
// ---------------------------------------------------------------------------
__global__ __launch_bounds__(256, 3) void attn_kernel(
    const void* __restrict__ valid_len,
    const float* __restrict__ W_score)
{
    __shared__ uint4 qpu[4][32];         // 4 queries x 256 halves
    __shared__ float ws[DD];
    __shared__ float sl[4][KN];
    __shared__ float red[9];

    const int tid = threadIdx.x;
    const int b  = blockIdx.x >> 5;
    const int q0 = (blockIdx.x & 31) * 4;

    ws[tid] = W_score[tid];
    if (tid < 128) {
        int j = tid >> 5, c = tid & 31;
        qpu[j][c] = ((const uint4*)(g_qproj + (size_t)(b * QN + q0 + j) * DD))[c];
    }

    int vl;
    {
        const int* w32 = (const int*)valid_len;
        bool is64 = ((w32[1] | w32[3] | w32[5] | w32[7]) == 0);
        vl = is64 ? (int)(((const long long*)valid_len)[b]) : w32[b];
    }
    __syncthreads();

    #pragma unroll
    for (int rep = 0; rep < 2; rep++) {
        const int k = tid + rep * 256;
        const uint4* kp = (const uint4*)g_kprojT + (b * 32) * KN + k;  // +c*KN per chunk
        float acc[4] = {};
        #pragma unroll 4
        for (int c = 0; c < 32; c++) {
            uint4 kv = kp[c * KN];
            const float4 wa = *(const float4*)&ws[c * 8];
            const float4 wb = *(const float4*)&ws[c * 8 + 4];
            #pragma unroll
            for (int j = 0; j < 4; j++) {
                uint4 qv = qpu[j][c];
                #pragma unroll
                for (int p = 0; p < 4; p++) {
                    unsigned int t = htanh2(hadd2u((&qv.x)[p], (&kv.x)[p]));
                    float2 f = __half22float2(*(__half2*)&t);
                    float wlo = (p == 0) ? wa.x : (p == 1) ? wa.z : (p == 2) ? wb.x : wb.z;
                    float whi = (p == 0) ? wa.y : (p == 1) ? wa.w : (p == 2) ? wb.y : wb.w;
                    acc[j] = fmaf(wlo, f.x, acc[j]);
                    acc[j] = fmaf(whi, f.y, acc[j]);
                }
            }
        }
        const bool valid = (k < vl);
        #pragma unroll
        for (int j = 0; j < 4; j++)
            sl[j][k] = valid ? acc[j] : NEGC;
    }
    __syncthreads();

    #pragma unroll
    for (int j = 0; j < 4; j++) {
        float a = sl[j][tid];
        float c = sl[j][tid + 256];
        float m = fmaxf(a, c);
        #pragma unroll
        for (int o = 16; o; o >>= 1)
            m = fmaxf(m, __shfl_xor_sync(0xFFFFFFFFu, m, o));
        if ((tid & 31) == 0) red[tid >> 5] = m;
        __syncthreads();
        if (tid == 0) {
            float mm = red[0];
            #pragma unroll
            for (int i = 1; i < 8; i++) mm = fmaxf(mm, red[i]);
            red[8] = mm;
        }
        __syncthreads();
        m = red[8];
        float e0 = __expf(a - m);
        float e1 = __expf(c - m);
        float s = e0 + e1;
        #pragma unroll
        for (int o = 16; o; o >>= 1)
            s += __shfl_xor_sync(0xFFFFFFFFu, s, o);
        if ((tid & 31) == 0) red[tid >> 5] = s;
        __syncthreads();
        if (tid == 0) {
            float ss = 0.f;
            #pragma unroll
            for (int i = 0; i < 8; i++) ss += red[i];
            red[8] = ss;
        }
        __syncthreads();
        float inv = 1.0f / red[8];
        float* arow = &g_atten[(size_t)(b * QN + q0 + j) * KN];
        arow[tid]       = e0 * inv;
        arow[tid + 256] = e1 * inv;
        __syncthreads();
    }
}

// ---------------------------------------------------------------------------
// Kernel 3: GEMV out[b,q,v] = sum_k atten[b,q,k] * values[b,k,v].
// Block = (b, 16 q, 64 v), 128 threads, thread tile 4q x 2v.
// ---------------------------------------------------------------------------
__global__ __launch_bounds__(128, 8) void gemv_kernel(
    const float* __restrict__ values,
    float* __restrict__ out)
{
    __shared__ float a_sh[16][129];

    const int tid = threadIdx.x;
    const int v0 = blockIdx.x * 64;
    const int qb = blockIdx.y * 16;
    const int b  = blockIdx.z;

    const int qg = tid >> 5;             // 0..3 -> 4 q each
    const int vp = tid & 31;             // 0..31 -> 2 v each

    float acc[4][2] = {};

    for (int kc = 0; kc < 4; kc++) {
        #pragma unroll
        for (int i = 0; i < 4; i++) {
            int idx = tid + i * 128;
            int q = idx >> 5, c = idx & 31;
            float4 v4 = *(const float4*)&g_atten[(size_t)(b * QN + qb + q) * KN + kc * 128 + c * 4];
            a_sh[q][c * 4 + 0] = v4.x;
            a_sh[q][c * 4 + 1] = v4.y;
            a_sh[q][c * 4 + 2] = v4.z;
            a_sh[q][c * 4 + 3] = v4.w;
        }
        __syncthreads();

        const float* vptr = values + ((size_t)(b * KN + kc * 128)) * DD + v0 + vp * 2;
        #pragma unroll 8
        for (int kk = 0; kk < 128; kk++) {
            float2 vv = *(const float2*)(vptr + (size_t)kk * DD);
            #pragma unroll
            for (int i = 0; i < 4; i++) {
                float a = a_sh[qg * 4 + i][kk];
                acc[i][0] = fmaf(a, vv.x, acc[i][0]);
                acc[i][1] = fmaf(a, vv.y, acc[i][1]);
            }
        }
        __syncthreads();
    }

    #pragma unroll
    for (int i = 0; i < 4; i++) {
        float2* dst = (float2*)&out[(size_t)(b * QN + qb + qg * 4 + i) * DD + v0 + vp * 2];
        *dst = make_float2(acc[i][0], acc[i][1]);
    }
}

extern "C" void kernel_launch(void* const* d_in, const int* in_sizes, int n_in,
                              void* d_out, int out_size)
{
    const float* keys     = (const float*)d_in[0];
    const float* values   = (const float*)d_in[1];
    const float* queries  = (const float*)d_in[2];
    const void*  valid    = d_in[3];
    const float* W_hidden = (const float*)d_in[4];
    const float* W_score  = (const float*)d_in[5];
    float* out = (float*)d_out;

    proj_kernel<<<dim3(80, 4), 256>>>(queries, keys, W_hidden);
    attn_kernel<<<BB * (QN / 4), 256>>>(valid, W_score);
    gemv_kernel<<<dim3(4, 8, 8), 128>>>(values, out);
}